// round 8
// baseline (speedup 1.0000x reference)
#include <cuda_runtime.h>
#include <cuda_fp16.h>
#include <cstdint>

#define BATCH   2
#define SEQ     2048
#define CDIM    768
#define HEADS   12
#define HDIM    64
#define QKV_N   2304
#define MROWS   4096
#define BH      24
#define SCALEF  0.125f

// ---------------------------------------------------------------------------
// Scratch (fp16 hi/lo split everywhere)
// ---------------------------------------------------------------------------
__device__ __half g_x_hi[MROWS * CDIM];
__device__ __half g_x_lo[MROWS * CDIM];
__device__ __half g_wqkv_hi[QKV_N * CDIM];
__device__ __half g_wqkv_lo[QKV_N * CDIM];
__device__ __half g_wproj_hi[CDIM * CDIM];
__device__ __half g_wproj_lo[CDIM * CDIM];
__device__ __half g_q_hi[BH * SEQ * HDIM];    // [b,h,n,d], pre-scaled by 1/8
__device__ __half g_q_lo[BH * SEQ * HDIM];
__device__ __half g_k_hi[BH * SEQ * HDIM];
__device__ __half g_k_lo[BH * SEQ * HDIM];
__device__ __half g_vt_hi[BH * HDIM * SEQ];   // [b,h,d,n]
__device__ __half g_vt_lo[BH * HDIM * SEQ];
__device__ __half g_ctx_hi[MROWS * CDIM];
__device__ __half g_ctx_lo[MROWS * CDIM];

// ---------------------------------------------------------------------------
// Helpers (plain sm_80-era PTX)
// ---------------------------------------------------------------------------
__device__ __forceinline__ uint32_t smem_u32(const void* p) {
    uint32_t a;
    asm("{ .reg .u64 t; cvta.to.shared.u64 t, %1; cvt.u32.u64 %0, t; }" : "=r"(a) : "l"(p));
    return a;
}
__device__ __forceinline__ void cp16(uint32_t dst, const void* src) {
    asm volatile("cp.async.cg.shared.global [%0], [%1], 16;" :: "r"(dst), "l"(src));
}
__device__ __forceinline__ void cp_commit() { asm volatile("cp.async.commit_group;"); }
template <int N> __device__ __forceinline__ void cp_wait() {
    asm volatile("cp.async.wait_group %0;" :: "n"(N));
}
__device__ __forceinline__ void ldsm4(uint32_t a, uint32_t& r0, uint32_t& r1, uint32_t& r2, uint32_t& r3) {
    asm volatile("ldmatrix.sync.aligned.m8n8.x4.shared.b16 {%0,%1,%2,%3}, [%4];"
                 : "=r"(r0), "=r"(r1), "=r"(r2), "=r"(r3) : "r"(a));
}
// main pass: fp16 inputs, fp32 accumulate
__device__ __forceinline__ void mma_f32(float* c, const uint32_t* a, const uint32_t* b) {
    asm volatile("mma.sync.aligned.m16n8k16.row.col.f32.f16.f16.f32 "
                 "{%0,%1,%2,%3}, {%4,%5,%6,%7}, {%8,%9}, {%0,%1,%2,%3};"
                 : "+f"(c[0]), "+f"(c[1]), "+f"(c[2]), "+f"(c[3])
                 : "r"(a[0]), "r"(a[1]), "r"(a[2]), "r"(a[3]), "r"(b[0]), "r"(b[1]));
}
// correction pass: fp16 inputs, fp16 accumulate (half-cost)
__device__ __forceinline__ void mma_f16(uint32_t* c, const uint32_t* a, const uint32_t* b) {
    asm volatile("mma.sync.aligned.m16n8k16.row.col.f16.f16.f16.f16 "
                 "{%0,%1}, {%2,%3,%4,%5}, {%6,%7}, {%0,%1};"
                 : "+r"(c[0]), "+r"(c[1])
                 : "r"(a[0]), "r"(a[1]), "r"(a[2]), "r"(a[3]), "r"(b[0]), "r"(b[1]));
}
// split fp32 pair into fp16 hi/lo packed regs
__device__ __forceinline__ void split2h(float x, float y, uint32_t& hi, uint32_t& lo) {
    __half hx = __float2half_rn(x), hy = __float2half_rn(y);
    __half lx = __float2half_rn(x - __half2float(hx));
    __half ly = __float2half_rn(y - __half2float(hy));
    __half2 H = __halves2half2(hx, hy);
    __half2 L = __halves2half2(lx, ly);
    hi = *reinterpret_cast<uint32_t*>(&H);
    lo = *reinterpret_cast<uint32_t*>(&L);
}
__device__ __forceinline__ void fold2(uint32_t v, float& a, float& b) {
    float2 f = __half22float2(*reinterpret_cast<__half2*>(&v));
    a += f.x; b += f.y;
}

// ---------------------------------------------------------------------------
// Convert fp32 -> split fp16
// ---------------------------------------------------------------------------
__global__ void convert_split(const float* __restrict__ src,
                              __half* __restrict__ hi,
                              __half* __restrict__ lo, int n)
{
    int i = blockIdx.x * blockDim.x + threadIdx.x;
    for (; i < n; i += gridDim.x * blockDim.x) {
        float v = src[i];
        __half h = __float2half_rn(v);
        hi[i] = h;
        lo[i] = __float2half_rn(v - __half2float(h));
    }
}

// ---------------------------------------------------------------------------
// GEMM core: C(128x128) = (Ah+Al)(Bh+Bl)^T over K=768. 512 threads, 16 warps,
// warp tile 64x16. Main pass f32acc, corrections into shared f16 accumulator.
// smem stage: [Ahi 10240][Alo 10240][Bhi 10240][Blo 10240], rows 80B pitch.
// ---------------------------------------------------------------------------
#define GSTAGE   40960
#define G_ALO    10240
#define G_BHI    20480
#define G_BLO    30720
#define GEMM_SMEM (2 * GSTAGE)

__device__ __forceinline__ void gemm_load_stage(
    uint32_t sb, const __half* Ahi, const __half* Alo,
    const __half* Bhi, const __half* Blo,
    int m0, int n0, int k0, int tid)
{
    const int row = tid >> 2;                  // 0..127
    const int cb  = (tid & 3) * 16;            // 0..48 byte offset
    const size_t ga = (size_t)(m0 + row) * CDIM + k0;
    const size_t gb = (size_t)(n0 + row) * CDIM + k0;
    const uint32_t so = (uint32_t)row * 80 + cb;
    cp16(sb + so,          (const char*)(Ahi + ga) + cb);
    cp16(sb + G_ALO + so,  (const char*)(Alo + ga) + cb);
    cp16(sb + G_BHI + so,  (const char*)(Bhi + gb) + cb);
    cp16(sb + G_BLO + so,  (const char*)(Blo + gb) + cb);
}

__device__ __forceinline__ void gemm_core(
    char* smem, const __half* Ahi, const __half* Alo,
    const __half* Bhi, const __half* Blo,
    int m0, int n0, float c[4][2][4], uint32_t c16[4][2][2])
{
    const int tid = threadIdx.x;
    const int lane = tid & 31;
    const int wid = tid >> 5;                  // 0..15
    const int wm = wid >> 3, wn = wid & 7;     // 2 x 8 warp grid
    const uint32_t sb = smem_u32(smem);

    const uint32_t a_lrow = lane % 16, a_koff = (lane >> 4) * 16;
    const uint32_t b_lrow = (lane % 8) + ((lane >> 4) << 3), b_koff = ((lane >> 3) & 1) * 16;

#pragma unroll
    for (int i = 0; i < 4; i++)
#pragma unroll
        for (int j = 0; j < 2; j++) {
#pragma unroll
            for (int e = 0; e < 4; e++) c[i][j][e] = 0.0f;
            c16[i][j][0] = 0u; c16[i][j][1] = 0u;
        }

    gemm_load_stage(sb, Ahi, Alo, Bhi, Blo, m0, n0, 0, tid);
    cp_commit();

    for (int it = 0; it < 24; it++) {
        cp_wait<0>();
        __syncthreads();
        if (it + 1 < 24) {
            gemm_load_stage(sb + ((it + 1) & 1) * GSTAGE, Ahi, Alo, Bhi, Blo,
                            m0, n0, (it + 1) * 32, tid);
            cp_commit();
        }
        const uint32_t st = sb + (it & 1) * GSTAGE;
#pragma unroll
        for (int ks = 0; ks < 2; ks++) {
            uint32_t bh[2][2], bl[2][2];
            {
                uint32_t addr = st + G_BHI + (uint32_t)(wn * 16 + b_lrow) * 80 + ks * 32 + b_koff;
                ldsm4(addr, bh[0][0], bh[0][1], bh[1][0], bh[1][1]);
                ldsm4(addr + (G_BLO - G_BHI), bl[0][0], bl[0][1], bl[1][0], bl[1][1]);
            }
#pragma unroll
            for (int mf = 0; mf < 4; mf++) {
                uint32_t ah[4], al[4];
                uint32_t addr = st + (uint32_t)(wm * 64 + mf * 16 + a_lrow) * 80 + ks * 32 + a_koff;
                ldsm4(addr, ah[0], ah[1], ah[2], ah[3]);
                ldsm4(addr + G_ALO, al[0], al[1], al[2], al[3]);
                mma_f32(c[mf][0], ah, bh[0]);
                mma_f32(c[mf][1], ah, bh[1]);
                mma_f16(c16[mf][0], ah, bl[0]);
                mma_f16(c16[mf][1], ah, bl[1]);
                mma_f16(c16[mf][0], al, bh[0]);
                mma_f16(c16[mf][1], al, bh[1]);
            }
        }
    }
    // fold f16 corrections into f32 accumulators
#pragma unroll
    for (int mf = 0; mf < 4; mf++)
#pragma unroll
        for (int nf = 0; nf < 2; nf++) {
            fold2(c16[mf][nf][0], c[mf][nf][0], c[mf][nf][1]);
            fold2(c16[mf][nf][1], c[mf][nf][2], c[mf][nf][3]);
        }
}

// ---------------------------------------------------------------------------
// QKV GEMM: grid (2304/128=18, 4096/128=32), 512 threads
// ---------------------------------------------------------------------------
__device__ __forceinline__ void qkv_store(int s, int rowg, int colg, float v0, float v1)
{
    const int b = rowg >> 11, n = rowg & 2047;
    const int rem = colg - s * CDIM;
    const int h = rem >> 6, d = rem & 63;
    if (s == 0) { v0 *= SCALEF; v1 *= SCALEF; }
    __half h0 = __float2half_rn(v0), h1 = __float2half_rn(v1);
    __half l0 = __float2half_rn(v0 - __half2float(h0));
    __half l1 = __float2half_rn(v1 - __half2float(h1));
    if (s == 2) {
        const size_t base = ((size_t)(b * HEADS + h) * HDIM) * SEQ;
        g_vt_hi[base + (size_t)d * SEQ + n]       = h0;
        g_vt_hi[base + (size_t)(d + 1) * SEQ + n] = h1;
        g_vt_lo[base + (size_t)d * SEQ + n]       = l0;
        g_vt_lo[base + (size_t)(d + 1) * SEQ + n] = l1;
    } else {
        const size_t off = ((size_t)(b * HEADS + h) * SEQ + n) * HDIM + d;
        __half* dh = (s == 0) ? g_q_hi : g_k_hi;
        __half* dl = (s == 0) ? g_q_lo : g_k_lo;
        __half2 H = __halves2half2(h0, h1);
        __half2 L = __halves2half2(l0, l1);
        *reinterpret_cast<__half2*>(dh + off) = H;
        *reinterpret_cast<__half2*>(dl + off) = L;
    }
}

__global__ __launch_bounds__(512, 1) void qkv_mma()
{
    extern __shared__ char smem[];
    const int n0 = blockIdx.x * 128;
    const int m0 = blockIdx.y * 128;
    const int lane = threadIdx.x & 31;
    const int wid = threadIdx.x >> 5;
    const int wm = wid >> 3, wn = wid & 7;

    float c[4][2][4];
    uint32_t c16[4][2][2];
    gemm_core(smem, g_x_hi, g_x_lo, g_wqkv_hi, g_wqkv_lo, m0, n0, c, c16);

    const int s = n0 / CDIM;
#pragma unroll
    for (int mf = 0; mf < 4; mf++)
#pragma unroll
        for (int nf = 0; nf < 2; nf++) {
            const int rg = m0 + wm * 64 + mf * 16 + (lane >> 2);
            const int cg = n0 + wn * 16 + nf * 8 + (lane & 3) * 2;
            qkv_store(s, rg,     cg, c[mf][nf][0], c[mf][nf][1]);
            qkv_store(s, rg + 8, cg, c[mf][nf][2], c[mf][nf][3]);
        }
}

// ---------------------------------------------------------------------------
// Output projection: grid (768/128=6, 4096/128=32), 512 threads
// ---------------------------------------------------------------------------
__global__ __launch_bounds__(512, 1) void proj_mma(const float* __restrict__ bias,
                                                   float* __restrict__ out)
{
    extern __shared__ char smem[];
    const int n0 = blockIdx.x * 128;
    const int m0 = blockIdx.y * 128;
    const int lane = threadIdx.x & 31;
    const int wid = threadIdx.x >> 5;
    const int wm = wid >> 3, wn = wid & 7;

    float c[4][2][4];
    uint32_t c16[4][2][2];
    gemm_core(smem, g_ctx_hi, g_ctx_lo, g_wproj_hi, g_wproj_lo, m0, n0, c, c16);

#pragma unroll
    for (int mf = 0; mf < 4; mf++)
#pragma unroll
        for (int nf = 0; nf < 2; nf++) {
            const int rg = m0 + wm * 64 + mf * 16 + (lane >> 2);
            const int cg = n0 + wn * 16 + nf * 8 + (lane & 3) * 2;
            const float b0 = bias[cg], b1 = bias[cg + 1];
            float2 v0 = make_float2(c[mf][nf][0] + b0, c[mf][nf][1] + b1);
            float2 v1 = make_float2(c[mf][nf][2] + b0, c[mf][nf][3] + b1);
            *reinterpret_cast<float2*>(out + (size_t)rg * CDIM + cg) = v0;
            *reinterpret_cast<float2*>(out + (size_t)(rg + 8) * CDIM + cg) = v1;
        }
}

// ---------------------------------------------------------------------------
// Flash attention. 256 threads, 8 warps, warp = 16 q-rows. (256,1).
// fp16 3-pass: main f32acc, corrections f16acc (s16/o16, folded per tile).
// smem: Qhi 18432 | Qlo 18432 | 2 stages x [Khi|Klo|Vthi|Vtlo] (9216 each)
// ---------------------------------------------------------------------------
#define AQ_LO    18432
#define AKV      36864
#define ASTAGE   36864
#define AK_LO    9216
#define AV_HI    18432
#define AV_LO    27648
#define ATTN_SMEM (AKV + 2 * ASTAGE)   // 110592

__device__ __forceinline__ void attn_load_stage(
    uint32_t sb, const __half* Kh, const __half* Kl,
    const __half* Vh, const __half* Vl, int kv0, int tid)
{
    const int row = tid >> 2;
    const int cb  = (tid & 3) * 32;
    const uint32_t so = (uint32_t)row * 144 + cb;
    const char* kh = (const char*)(Kh + (size_t)(kv0 + row) * HDIM) + cb;
    const char* kl = (const char*)(Kl + (size_t)(kv0 + row) * HDIM) + cb;
    const char* vh = (const char*)(Vh + (size_t)row * SEQ + kv0) + cb;
    const char* vl = (const char*)(Vl + (size_t)row * SEQ + kv0) + cb;
    cp16(sb + so, kh);            cp16(sb + so + 16, kh + 16);
    cp16(sb + AK_LO + so, kl);    cp16(sb + AK_LO + so + 16, kl + 16);
    cp16(sb + AV_HI + so, vh);    cp16(sb + AV_HI + so + 16, vh + 16);
    cp16(sb + AV_LO + so, vl);    cp16(sb + AV_LO + so + 16, vl + 16);
}

__global__ __launch_bounds__(256, 1) void attn_mma()
{
    extern __shared__ char smem[];
    const uint32_t sb = smem_u32(smem);
    const int q0 = blockIdx.x * 128;
    const int bh = blockIdx.y;
    const int tid = threadIdx.x;
    const int lane = tid & 31;
    const int wid = tid >> 5;

    const __half* Qh = g_q_hi + (size_t)bh * SEQ * HDIM;
    const __half* Ql = g_q_lo + (size_t)bh * SEQ * HDIM;
    const __half* Kh = g_k_hi + (size_t)bh * SEQ * HDIM;
    const __half* Kl = g_k_lo + (size_t)bh * SEQ * HDIM;
    const __half* Vh = g_vt_hi + (size_t)bh * HDIM * SEQ;
    const __half* Vl = g_vt_lo + (size_t)bh * HDIM * SEQ;

    // Load Q tile into smem (144B pitch)
    {
        const int row = tid >> 1;
        const int cb = (tid & 1) * 64;
        const uint4* qs = reinterpret_cast<const uint4*>((const char*)(Qh + (size_t)(q0 + row) * HDIM) + cb);
        const uint4* ql = reinterpret_cast<const uint4*>((const char*)(Ql + (size_t)(q0 + row) * HDIM) + cb);
        uint4* dh = reinterpret_cast<uint4*>(smem + (uint32_t)row * 144 + cb);
        uint4* dl = reinterpret_cast<uint4*>(smem + AQ_LO + (uint32_t)row * 144 + cb);
#pragma unroll
        for (int i = 0; i < 4; i++) { dh[i] = qs[i]; dl[i] = ql[i]; }
    }
    attn_load_stage(sb + AKV, Kh, Kl, Vh, Vl, 0, tid);
    cp_commit();
    __syncthreads();

    const uint32_t a_lrow = lane % 16, a_koff = (lane >> 4) * 16;
    const uint32_t b_lrow = (lane % 8) + ((lane >> 4) << 3), b_koff = ((lane >> 3) & 1) * 16;

    // Qh fragments resident; Ql re-loaded per ks (register relief)
    uint32_t qh[4][4];
#pragma unroll
    for (int ks = 0; ks < 4; ks++) {
        uint32_t addr = sb + (uint32_t)(wid * 16 + a_lrow) * 144 + ks * 32 + a_koff;
        ldsm4(addr, qh[ks][0], qh[ks][1], qh[ks][2], qh[ks][3]);
    }

    float o[8][4];
#pragma unroll
    for (int nf = 0; nf < 8; nf++)
#pragma unroll
        for (int e = 0; e < 4; e++) o[nf][e] = 0.0f;
    float m_run0 = -1e30f, m_run1 = -1e30f, l_run0 = 0.0f, l_run1 = 0.0f;

    for (int it = 0; it < SEQ / 64; it++) {
        cp_wait<0>();
        __syncthreads();
        if (it + 1 < SEQ / 64) {
            attn_load_stage(sb + AKV + ((it + 1) & 1) * ASTAGE, Kh, Kl, Vh, Vl, (it + 1) * 64, tid);
            cp_commit();
        }
        const uint32_t st = sb + AKV + (it & 1) * ASTAGE;

        // ---- S = Q K^T : main f32acc + corrections f16acc ----
        float s[8][4];
        uint32_t s16[8][2];
#pragma unroll
        for (int nf = 0; nf < 8; nf++) {
#pragma unroll
            for (int e = 0; e < 4; e++) s[nf][e] = 0.0f;
            s16[nf][0] = 0u; s16[nf][1] = 0u;
        }
#pragma unroll
        for (int ks = 0; ks < 4; ks++) {
            uint32_t kbh[8][2], kbl[8][2], ql[4];
#pragma unroll
            for (int nfp = 0; nfp < 4; nfp++) {
                uint32_t addr = st + (uint32_t)(nfp * 16 + b_lrow) * 144 + ks * 32 + b_koff;
                ldsm4(addr, kbh[2 * nfp][0], kbh[2 * nfp][1], kbh[2 * nfp + 1][0], kbh[2 * nfp + 1][1]);
                ldsm4(addr + AK_LO, kbl[2 * nfp][0], kbl[2 * nfp][1], kbl[2 * nfp + 1][0], kbl[2 * nfp + 1][1]);
            }
            {
                uint32_t addr = sb + AQ_LO + (uint32_t)(wid * 16 + a_lrow) * 144 + ks * 32 + a_koff;
                ldsm4(addr, ql[0], ql[1], ql[2], ql[3]);
            }
#pragma unroll
            for (int nf = 0; nf < 8; nf++) mma_f32(s[nf], qh[ks], kbh[nf]);
#pragma unroll
            for (int nf = 0; nf < 8; nf++) mma_f16(s16[nf], qh[ks], kbl[nf]);
#pragma unroll
            for (int nf = 0; nf < 8; nf++) mma_f16(s16[nf], ql, kbh[nf]);
        }
#pragma unroll
        for (int nf = 0; nf < 8; nf++) {
            fold2(s16[nf][0], s[nf][0], s[nf][1]);
            fold2(s16[nf][1], s[nf][2], s[nf][3]);
        }

        // ---- online softmax ----
        float vm0 = -1e30f, vm1 = -1e30f;
#pragma unroll
        for (int nf = 0; nf < 8; nf++) {
            vm0 = fmaxf(vm0, fmaxf(s[nf][0], s[nf][1]));
            vm1 = fmaxf(vm1, fmaxf(s[nf][2], s[nf][3]));
        }
        vm0 = fmaxf(vm0, __shfl_xor_sync(0xffffffff, vm0, 1));
        vm0 = fmaxf(vm0, __shfl_xor_sync(0xffffffff, vm0, 2));
        vm1 = fmaxf(vm1, __shfl_xor_sync(0xffffffff, vm1, 1));
        vm1 = fmaxf(vm1, __shfl_xor_sync(0xffffffff, vm1, 2));
        const float nm0 = fmaxf(m_run0, vm0);
        const float nm1 = fmaxf(m_run1, vm1);
        const float corr0 = __expf(m_run0 - nm0);
        const float corr1 = __expf(m_run1 - nm1);
        float sum0 = 0.0f, sum1 = 0.0f;
#pragma unroll
        for (int nf = 0; nf < 8; nf++) {
            s[nf][0] = __expf(s[nf][0] - nm0); sum0 += s[nf][0];
            s[nf][1] = __expf(s[nf][1] - nm0); sum0 += s[nf][1];
            s[nf][2] = __expf(s[nf][2] - nm1); sum1 += s[nf][2];
            s[nf][3] = __expf(s[nf][3] - nm1); sum1 += s[nf][3];
        }
        sum0 += __shfl_xor_sync(0xffffffff, sum0, 1);
        sum0 += __shfl_xor_sync(0xffffffff, sum0, 2);
        sum1 += __shfl_xor_sync(0xffffffff, sum1, 1);
        sum1 += __shfl_xor_sync(0xffffffff, sum1, 2);
        l_run0 = l_run0 * corr0 + sum0;
        l_run1 = l_run1 * corr1 + sum1;
        m_run0 = nm0; m_run1 = nm1;
#pragma unroll
        for (int nf = 0; nf < 8; nf++) {
            o[nf][0] *= corr0; o[nf][1] *= corr0;
            o[nf][2] *= corr1; o[nf][3] *= corr1;
        }

        // ---- O += P V : main f32acc + corrections f16acc ----
        uint32_t o16[8][2];
#pragma unroll
        for (int nf = 0; nf < 8; nf++) { o16[nf][0] = 0u; o16[nf][1] = 0u; }
#pragma unroll
        for (int ks2 = 0; ks2 < 4; ks2++) {
            uint32_t pah[4], pal[4];
            split2h(s[2 * ks2][0],     s[2 * ks2][1],     pah[0], pal[0]);
            split2h(s[2 * ks2][2],     s[2 * ks2][3],     pah[1], pal[1]);
            split2h(s[2 * ks2 + 1][0], s[2 * ks2 + 1][1], pah[2], pal[2]);
            split2h(s[2 * ks2 + 1][2], s[2 * ks2 + 1][3], pah[3], pal[3]);
            uint32_t vbh[8][2], vbl[8][2];
#pragma unroll
            for (int nfp = 0; nfp < 4; nfp++) {
                uint32_t addr = st + AV_HI + (uint32_t)(nfp * 16 + b_lrow) * 144 + ks2 * 32 + b_koff;
                ldsm4(addr, vbh[2 * nfp][0], vbh[2 * nfp][1], vbh[2 * nfp + 1][0], vbh[2 * nfp + 1][1]);
                ldsm4(addr + (AV_LO - AV_HI), vbl[2 * nfp][0], vbl[2 * nfp][1], vbl[2 * nfp + 1][0], vbl[2 * nfp + 1][1]);
            }
#pragma unroll
            for (int nf = 0; nf < 8; nf++) mma_f32(o[nf], pah, vbh[nf]);
#pragma unroll
            for (int nf = 0; nf < 8; nf++) mma_f16(o16[nf], pah, vbl[nf]);
#pragma unroll
            for (int nf = 0; nf < 8; nf++) mma_f16(o16[nf], pal, vbh[nf]);
        }
#pragma unroll
        for (int nf = 0; nf < 8; nf++) {
            fold2(o16[nf][0], o[nf][0], o[nf][1]);
            fold2(o16[nf][1], o[nf][2], o[nf][3]);
        }
    }

    // ---- epilogue: normalize, split, write ctx ----
    const int b = bh / HEADS;
    const int h = bh % HEADS;
    const float inv0 = 1.0f / l_run0;
    const float inv1 = 1.0f / l_run1;
    const int r0 = q0 + wid * 16 + (lane >> 2);
#pragma unroll
    for (int nf = 0; nf < 8; nf++) {
        const int d = nf * 8 + (lane & 3) * 2;
        uint32_t H, L;
        split2h(o[nf][0] * inv0, o[nf][1] * inv0, H, L);
        size_t off = ((size_t)(b * SEQ + r0)) * CDIM + h * HDIM + d;
        *reinterpret_cast<uint32_t*>(g_ctx_hi + off) = H;
        *reinterpret_cast<uint32_t*>(g_ctx_lo + off) = L;
        split2h(o[nf][2] * inv1, o[nf][3] * inv1, H, L);
        off = ((size_t)(b * SEQ + r0 + 8)) * CDIM + h * HDIM + d;
        *reinterpret_cast<uint32_t*>(g_ctx_hi + off) = H;
        *reinterpret_cast<uint32_t*>(g_ctx_lo + off) = L;
    }
}

// ---------------------------------------------------------------------------
// Launch
// ---------------------------------------------------------------------------
extern "C" void kernel_launch(void* const* d_in, const int* in_sizes, int n_in,
                              void* d_out, int out_size)
{
    const float* x      = (const float*)d_in[0];
    const float* w_qkv  = (const float*)d_in[1];
    const float* w_proj = (const float*)d_in[2];
    const float* b_proj = (const float*)d_in[3];
    float* out = (float*)d_out;
    (void)in_sizes; (void)n_in; (void)out_size;

    cudaFuncSetAttribute(qkv_mma,  cudaFuncAttributeMaxDynamicSharedMemorySize, GEMM_SMEM);
    cudaFuncSetAttribute(attn_mma, cudaFuncAttributeMaxDynamicSharedMemorySize, ATTN_SMEM);
    cudaFuncSetAttribute(proj_mma, cudaFuncAttributeMaxDynamicSharedMemorySize, GEMM_SMEM);

    __half *xh, *xl, *wh, *wl, *ph, *pl;
    cudaGetSymbolAddress((void**)&xh, g_x_hi);
    cudaGetSymbolAddress((void**)&xl, g_x_lo);
    cudaGetSymbolAddress((void**)&wh, g_wqkv_hi);
    cudaGetSymbolAddress((void**)&wl, g_wqkv_lo);
    cudaGetSymbolAddress((void**)&ph, g_wproj_hi);
    cudaGetSymbolAddress((void**)&pl, g_wproj_lo);

    convert_split<<<1024, 256>>>(x, xh, xl, MROWS * CDIM);
    convert_split<<<1024, 256>>>(w_qkv, wh, wl, QKV_N * CDIM);
    convert_split<<<512, 256>>>(w_proj, ph, pl, CDIM * CDIM);

    qkv_mma<<<dim3(QKV_N / 128, MROWS / 128), 512, GEMM_SMEM>>>();
    attn_mma<<<dim3(SEQ / 128, BH), 256, ATTN_SMEM>>>();
    proj_mma<<<dim3(CDIM / 128, MROWS / 128), 512, GEMM_SMEM>>>(b_proj, out);
}

// round 9
// speedup vs baseline: 1.6368x; 1.6368x over previous
#include <cuda_runtime.h>
#include <cuda_fp16.h>
#include <cstdint>

#define BATCH   2
#define SEQ     2048
#define CDIM    768
#define HEADS   12
#define HDIM    64
#define QKV_N   2304
#define MROWS   4096
#define BH      24
#define SCALEF  0.125f

// ---------------------------------------------------------------------------
// Scratch (fp16; lo terms only where used as B operands)
// ---------------------------------------------------------------------------
__device__ __half g_x_hi[MROWS * CDIM];
__device__ __half g_wqkv_hi[QKV_N * CDIM];
__device__ __half g_wqkv_lo[QKV_N * CDIM];
__device__ __half g_wproj_hi[CDIM * CDIM];
__device__ __half g_wproj_lo[CDIM * CDIM];
__device__ __half g_q_hi[BH * SEQ * HDIM];    // [b,h,n,d], pre-scaled by 1/8
__device__ __half g_k_hi[BH * SEQ * HDIM];
__device__ __half g_k_lo[BH * SEQ * HDIM];
__device__ __half g_vt_hi[BH * HDIM * SEQ];   // [b,h,d,n]
__device__ __half g_ctx_hi[MROWS * CDIM];

// ---------------------------------------------------------------------------
// Helpers
// ---------------------------------------------------------------------------
__device__ __forceinline__ uint32_t smem_u32(const void* p) {
    uint32_t a;
    asm("{ .reg .u64 t; cvta.to.shared.u64 t, %1; cvt.u32.u64 %0, t; }" : "=r"(a) : "l"(p));
    return a;
}
__device__ __forceinline__ void cp16(uint32_t dst, const void* src) {
    asm volatile("cp.async.cg.shared.global [%0], [%1], 16;" :: "r"(dst), "l"(src));
}
__device__ __forceinline__ void cp_commit() { asm volatile("cp.async.commit_group;"); }
template <int N> __device__ __forceinline__ void cp_wait() {
    asm volatile("cp.async.wait_group %0;" :: "n"(N));
}
__device__ __forceinline__ void ldsm4(uint32_t a, uint32_t& r0, uint32_t& r1, uint32_t& r2, uint32_t& r3) {
    asm volatile("ldmatrix.sync.aligned.m8n8.x4.shared.b16 {%0,%1,%2,%3}, [%4];"
                 : "=r"(r0), "=r"(r1), "=r"(r2), "=r"(r3) : "r"(a));
}
__device__ __forceinline__ void mma_f32(float* c, const uint32_t* a, const uint32_t* b) {
    asm volatile("mma.sync.aligned.m16n8k16.row.col.f32.f16.f16.f32 "
                 "{%0,%1,%2,%3}, {%4,%5,%6,%7}, {%8,%9}, {%0,%1,%2,%3};"
                 : "+f"(c[0]), "+f"(c[1]), "+f"(c[2]), "+f"(c[3])
                 : "r"(a[0]), "r"(a[1]), "r"(a[2]), "r"(a[3]), "r"(b[0]), "r"(b[1]));
}
__device__ __forceinline__ uint32_t pack2h(float x, float y) {
    __half2 H = __halves2half2(__float2half_rn(x), __float2half_rn(y));
    return *reinterpret_cast<uint32_t*>(&H);
}
__device__ __forceinline__ void split2h(float x, float y, uint32_t& hi, uint32_t& lo) {
    __half hx = __float2half_rn(x), hy = __float2half_rn(y);
    __half lx = __float2half_rn(x - __half2float(hx));
    __half ly = __float2half_rn(y - __half2float(hy));
    __half2 H = __halves2half2(hx, hy);
    __half2 L = __halves2half2(lx, ly);
    hi = *reinterpret_cast<uint32_t*>(&H);
    lo = *reinterpret_cast<uint32_t*>(&L);
}

// ---------------------------------------------------------------------------
// Converts
// ---------------------------------------------------------------------------
__global__ void convert_hi(const float* __restrict__ src, __half* __restrict__ hi, int n)
{
    int i = blockIdx.x * blockDim.x + threadIdx.x;
    for (; i < n; i += gridDim.x * blockDim.x)
        hi[i] = __float2half_rn(src[i]);
}
__global__ void convert_split(const float* __restrict__ src,
                              __half* __restrict__ hi, __half* __restrict__ lo, int n)
{
    int i = blockIdx.x * blockDim.x + threadIdx.x;
    for (; i < n; i += gridDim.x * blockDim.x) {
        float v = src[i];
        __half h = __float2half_rn(v);
        hi[i] = h;
        lo[i] = __float2half_rn(v - __half2float(h));
    }
}

// ---------------------------------------------------------------------------
// GEMM core: C(128x128) = Ah (Bh+Bl)^T over K=768. 256 threads, 8 warps,
// warp tile 64x32, 2 passes per chunk. smem stage: [Ahi][Bhi][Blo] @ 80B pitch.
// ---------------------------------------------------------------------------
#define GSTAGE   30720
#define G_BHI    10240
#define G_BLO    20480
#define GEMM_SMEM (2 * GSTAGE)

__device__ __forceinline__ void gemm_load_stage(
    uint32_t sb, const __half* Ahi, const __half* Bhi, const __half* Blo,
    int m0, int n0, int k0, int tid)
{
    const int row = tid >> 1;
    const int cb  = (tid & 1) * 32;
    const size_t ga = (size_t)(m0 + row) * CDIM + k0;
    const size_t gb = (size_t)(n0 + row) * CDIM + k0;
    const uint32_t so = (uint32_t)row * 80 + cb;
    cp16(sb + so,               (const char*)(Ahi + ga) + cb);
    cp16(sb + so + 16,          (const char*)(Ahi + ga) + cb + 16);
    cp16(sb + G_BHI + so,       (const char*)(Bhi + gb) + cb);
    cp16(sb + G_BHI + so + 16,  (const char*)(Bhi + gb) + cb + 16);
    cp16(sb + G_BLO + so,       (const char*)(Blo + gb) + cb);
    cp16(sb + G_BLO + so + 16,  (const char*)(Blo + gb) + cb + 16);
}

__device__ __forceinline__ void ld_afrag(uint32_t st, int wm, int step,
                                         uint32_t a_lrow, uint32_t a_koff, uint32_t* a)
{
    const int ks = step >> 2, mf = step & 3;
    uint32_t addr = st + (uint32_t)(wm * 64 + mf * 16 + a_lrow) * 80 + ks * 32 + a_koff;
    ldsm4(addr, a[0], a[1], a[2], a[3]);
}
__device__ __forceinline__ void ld_bfrag(uint32_t st, int wn, int ks,
                                         uint32_t b_lrow, uint32_t b_koff,
                                         uint32_t bh[4][2], uint32_t bl[4][2])
{
#pragma unroll
    for (int nfp = 0; nfp < 2; nfp++) {
        uint32_t addr = st + G_BHI + (uint32_t)(wn * 32 + nfp * 16 + b_lrow) * 80 + ks * 32 + b_koff;
        ldsm4(addr, bh[2 * nfp][0], bh[2 * nfp][1], bh[2 * nfp + 1][0], bh[2 * nfp + 1][1]);
        ldsm4(addr + (G_BLO - G_BHI), bl[2 * nfp][0], bl[2 * nfp][1], bl[2 * nfp + 1][0], bl[2 * nfp + 1][1]);
    }
}

__device__ __forceinline__ void gemm_core(
    char* smem, const __half* Ahi, const __half* Bhi, const __half* Blo,
    int m0, int n0, float c[4][4][4])
{
    const int tid = threadIdx.x;
    const int lane = tid & 31;
    const int wid = tid >> 5;
    const int wm = wid >> 2, wn = wid & 3;
    const uint32_t sb = smem_u32(smem);

    const uint32_t a_lrow = lane % 16, a_koff = (lane >> 4) * 16;
    const uint32_t b_lrow = (lane % 8) + ((lane >> 4) << 3), b_koff = ((lane >> 3) & 1) * 16;

#pragma unroll
    for (int i = 0; i < 4; i++)
#pragma unroll
        for (int j = 0; j < 4; j++)
#pragma unroll
            for (int e = 0; e < 4; e++) c[i][j][e] = 0.0f;

    gemm_load_stage(sb, Ahi, Bhi, Blo, m0, n0, 0, tid);
    cp_commit();

    uint32_t ar[2][4];
    uint32_t bhr[2][4][2], blr[2][4][2];

    for (int it = 0; it < 24; it++) {
        cp_wait<0>();
        __syncthreads();
        if (it + 1 < 24) {
            gemm_load_stage(sb + ((it + 1) & 1) * GSTAGE, Ahi, Bhi, Blo,
                            m0, n0, (it + 1) * 32, tid);
            cp_commit();
        }
        const uint32_t st = sb + (it & 1) * GSTAGE;

        ld_bfrag(st, wn, 0, b_lrow, b_koff, bhr[0], blr[0]);
        ld_afrag(st, wm, 0, a_lrow, a_koff, ar[0]);

#pragma unroll
        for (int ks = 0; ks < 2; ks++) {
            if (ks == 0)
                ld_bfrag(st, wn, 1, b_lrow, b_koff, bhr[1], blr[1]);
#pragma unroll
            for (int mf = 0; mf < 4; mf++) {
                const int step = ks * 4 + mf;
                if (step + 1 < 8)
                    ld_afrag(st, wm, step + 1, a_lrow, a_koff, ar[(step + 1) & 1]);
                const uint32_t* a = ar[step & 1];
#pragma unroll
                for (int nf = 0; nf < 4; nf++) {
                    mma_f32(c[mf][nf], a, bhr[ks][nf]);
                    mma_f32(c[mf][nf], a, blr[ks][nf]);
                }
            }
        }
    }
}

// ---------------------------------------------------------------------------
// QKV GEMM: grid (18, 32), 256 threads, 2 CTAs/SM
// ---------------------------------------------------------------------------
__device__ __forceinline__ void qkv_store(int s, int rowg, int colg, float v0, float v1)
{
    const int b = rowg >> 11, n = rowg & 2047;
    const int rem = colg - s * CDIM;
    const int h = rem >> 6, d = rem & 63;
    if (s == 0) {
        // q: scale, hi only
        const size_t off = ((size_t)(b * HEADS + h) * SEQ + n) * HDIM + d;
        *reinterpret_cast<uint32_t*>(g_q_hi + off) = pack2h(v0 * SCALEF, v1 * SCALEF);
    } else if (s == 1) {
        // k: hi + lo
        uint32_t H, L;
        split2h(v0, v1, H, L);
        const size_t off = ((size_t)(b * HEADS + h) * SEQ + n) * HDIM + d;
        *reinterpret_cast<uint32_t*>(g_k_hi + off) = H;
        *reinterpret_cast<uint32_t*>(g_k_lo + off) = L;
    } else {
        // v: hi only, transposed [b,h,d,n]
        const size_t base = ((size_t)(b * HEADS + h) * HDIM) * SEQ;
        g_vt_hi[base + (size_t)d * SEQ + n]       = __float2half_rn(v0);
        g_vt_hi[base + (size_t)(d + 1) * SEQ + n] = __float2half_rn(v1);
    }
}

__global__ __launch_bounds__(256, 2) void qkv_mma()
{
    extern __shared__ char smem[];
    const int n0 = blockIdx.x * 128;
    const int m0 = blockIdx.y * 128;
    const int lane = threadIdx.x & 31;
    const int wid = threadIdx.x >> 5;
    const int wm = wid >> 2, wn = wid & 3;

    float c[4][4][4];
    gemm_core(smem, g_x_hi, g_wqkv_hi, g_wqkv_lo, m0, n0, c);

    const int s = n0 / CDIM;
#pragma unroll
    for (int mf = 0; mf < 4; mf++)
#pragma unroll
        for (int nf = 0; nf < 4; nf++) {
            const int rg = m0 + wm * 64 + mf * 16 + (lane >> 2);
            const int cg = n0 + wn * 32 + nf * 8 + (lane & 3) * 2;
            qkv_store(s, rg,     cg, c[mf][nf][0], c[mf][nf][1]);
            qkv_store(s, rg + 8, cg, c[mf][nf][2], c[mf][nf][3]);
        }
}

// ---------------------------------------------------------------------------
// Output projection: grid (6, 32), 256 threads, 2 CTAs/SM
// ---------------------------------------------------------------------------
__global__ __launch_bounds__(256, 2) void proj_mma(const float* __restrict__ bias,
                                                   float* __restrict__ out)
{
    extern __shared__ char smem[];
    const int n0 = blockIdx.x * 128;
    const int m0 = blockIdx.y * 128;
    const int lane = threadIdx.x & 31;
    const int wid = threadIdx.x >> 5;
    const int wm = wid >> 2, wn = wid & 3;

    float c[4][4][4];
    gemm_core(smem, g_ctx_hi, g_wproj_hi, g_wproj_lo, m0, n0, c);

#pragma unroll
    for (int mf = 0; mf < 4; mf++)
#pragma unroll
        for (int nf = 0; nf < 4; nf++) {
            const int rg = m0 + wm * 64 + mf * 16 + (lane >> 2);
            const int cg = n0 + wn * 32 + nf * 8 + (lane & 3) * 2;
            const float b0 = bias[cg], b1 = bias[cg + 1];
            float2 v0 = make_float2(c[mf][nf][0] + b0, c[mf][nf][1] + b1);
            float2 v1 = make_float2(c[mf][nf][2] + b0, c[mf][nf][3] + b1);
            *reinterpret_cast<float2*>(out + (size_t)rg * CDIM + cg) = v0;
            *reinterpret_cast<float2*>(out + (size_t)(rg + 8) * CDIM + cg) = v1;
        }
}

// ---------------------------------------------------------------------------
// Flash attention: grid (16, 24), 256 threads, 2 CTAs/SM.
// QK = qh·(kh+kl) [2 passes]; PV = p16·vh [1 pass]. S/P in registers.
// smem: Qhi 18432 | 2 stages x [Khi 9216 | Klo 9216 | Vthi 9216]
// ---------------------------------------------------------------------------
#define AKV      18432
#define ASTAGE   27648
#define AK_LO    9216
#define AV_HI    18432
#define ATTN_SMEM (AKV + 2 * ASTAGE)   // 73728

__device__ __forceinline__ void attn_load_stage(
    uint32_t sb, const __half* Kh, const __half* Kl, const __half* Vh,
    int kv0, int tid)
{
    const int row = tid >> 2;                 // 0..63
    const int cb  = (tid & 3) * 32;
    const uint32_t so = (uint32_t)row * 144 + cb;
    const char* kh = (const char*)(Kh + (size_t)(kv0 + row) * HDIM) + cb;
    const char* kl = (const char*)(Kl + (size_t)(kv0 + row) * HDIM) + cb;
    const char* vh = (const char*)(Vh + (size_t)row * SEQ + kv0) + cb;
    cp16(sb + so, kh);            cp16(sb + so + 16, kh + 16);
    cp16(sb + AK_LO + so, kl);    cp16(sb + AK_LO + so + 16, kl + 16);
    cp16(sb + AV_HI + so, vh);    cp16(sb + AV_HI + so + 16, vh + 16);
}

__global__ __launch_bounds__(256, 2) void attn_mma()
{
    extern __shared__ char smem[];
    const uint32_t sb = smem_u32(smem);
    const int q0 = blockIdx.x * 128;
    const int bh = blockIdx.y;
    const int tid = threadIdx.x;
    const int lane = tid & 31;
    const int wid = tid >> 5;

    const __half* Qh = g_q_hi + (size_t)bh * SEQ * HDIM;
    const __half* Kh = g_k_hi + (size_t)bh * SEQ * HDIM;
    const __half* Kl = g_k_lo + (size_t)bh * SEQ * HDIM;
    const __half* Vh = g_vt_hi + (size_t)bh * HDIM * SEQ;

    // Load Q tile (144B pitch)
    {
        const int row = tid >> 1;
        const int cb = (tid & 1) * 64;
        const uint4* qs = reinterpret_cast<const uint4*>((const char*)(Qh + (size_t)(q0 + row) * HDIM) + cb);
        uint4* dh = reinterpret_cast<uint4*>(smem + (uint32_t)row * 144 + cb);
#pragma unroll
        for (int i = 0; i < 4; i++) dh[i] = qs[i];
    }
    attn_load_stage(sb + AKV, Kh, Kl, Vh, 0, tid);
    cp_commit();
    __syncthreads();

    const uint32_t a_lrow = lane % 16, a_koff = (lane >> 4) * 16;
    const uint32_t b_lrow = (lane % 8) + ((lane >> 4) << 3), b_koff = ((lane >> 3) & 1) * 16;

    uint32_t qh[4][4];
#pragma unroll
    for (int ks = 0; ks < 4; ks++) {
        uint32_t addr = sb + (uint32_t)(wid * 16 + a_lrow) * 144 + ks * 32 + a_koff;
        ldsm4(addr, qh[ks][0], qh[ks][1], qh[ks][2], qh[ks][3]);
    }

    float o[8][4];
#pragma unroll
    for (int nf = 0; nf < 8; nf++)
#pragma unroll
        for (int e = 0; e < 4; e++) o[nf][e] = 0.0f;
    float m_run0 = -1e30f, m_run1 = -1e30f, l_run0 = 0.0f, l_run1 = 0.0f;

    for (int it = 0; it < SEQ / 64; it++) {
        cp_wait<0>();
        __syncthreads();
        if (it + 1 < SEQ / 64) {
            attn_load_stage(sb + AKV + ((it + 1) & 1) * ASTAGE, Kh, Kl, Vh, (it + 1) * 64, tid);
            cp_commit();
        }
        const uint32_t st = sb + AKV + (it & 1) * ASTAGE;

        // ---- S = qh (kh + kl)^T  (2 passes) ----
        float s[8][4];
#pragma unroll
        for (int nf = 0; nf < 8; nf++)
#pragma unroll
            for (int e = 0; e < 4; e++) s[nf][e] = 0.0f;
#pragma unroll
        for (int ks = 0; ks < 4; ks++) {
            uint32_t kbh[8][2], kbl[8][2];
#pragma unroll
            for (int nfp = 0; nfp < 4; nfp++) {
                uint32_t addr = st + (uint32_t)(nfp * 16 + b_lrow) * 144 + ks * 32 + b_koff;
                ldsm4(addr, kbh[2 * nfp][0], kbh[2 * nfp][1], kbh[2 * nfp + 1][0], kbh[2 * nfp + 1][1]);
                ldsm4(addr + AK_LO, kbl[2 * nfp][0], kbl[2 * nfp][1], kbl[2 * nfp + 1][0], kbl[2 * nfp + 1][1]);
            }
#pragma unroll
            for (int nf = 0; nf < 8; nf++) {
                mma_f32(s[nf], qh[ks], kbh[nf]);
                mma_f32(s[nf], qh[ks], kbl[nf]);
            }
        }

        // ---- online softmax ----
        float vm0 = -1e30f, vm1 = -1e30f;
#pragma unroll
        for (int nf = 0; nf < 8; nf++) {
            vm0 = fmaxf(vm0, fmaxf(s[nf][0], s[nf][1]));
            vm1 = fmaxf(vm1, fmaxf(s[nf][2], s[nf][3]));
        }
        vm0 = fmaxf(vm0, __shfl_xor_sync(0xffffffff, vm0, 1));
        vm0 = fmaxf(vm0, __shfl_xor_sync(0xffffffff, vm0, 2));
        vm1 = fmaxf(vm1, __shfl_xor_sync(0xffffffff, vm1, 1));
        vm1 = fmaxf(vm1, __shfl_xor_sync(0xffffffff, vm1, 2));
        const float nm0 = fmaxf(m_run0, vm0);
        const float nm1 = fmaxf(m_run1, vm1);
        const float corr0 = __expf(m_run0 - nm0);
        const float corr1 = __expf(m_run1 - nm1);
        float sum0 = 0.0f, sum1 = 0.0f;
#pragma unroll
        for (int nf = 0; nf < 8; nf++) {
            s[nf][0] = __expf(s[nf][0] - nm0); sum0 += s[nf][0];
            s[nf][1] = __expf(s[nf][1] - nm0); sum0 += s[nf][1];
            s[nf][2] = __expf(s[nf][2] - nm1); sum1 += s[nf][2];
            s[nf][3] = __expf(s[nf][3] - nm1); sum1 += s[nf][3];
        }
        sum0 += __shfl_xor_sync(0xffffffff, sum0, 1);
        sum0 += __shfl_xor_sync(0xffffffff, sum0, 2);
        sum1 += __shfl_xor_sync(0xffffffff, sum1, 1);
        sum1 += __shfl_xor_sync(0xffffffff, sum1, 2);
        l_run0 = l_run0 * corr0 + sum0;
        l_run1 = l_run1 * corr1 + sum1;
        m_run0 = nm0; m_run1 = nm1;
#pragma unroll
        for (int nf = 0; nf < 8; nf++) {
            o[nf][0] *= corr0; o[nf][1] *= corr0;
            o[nf][2] *= corr1; o[nf][3] *= corr1;
        }

        // ---- O += p16 · vh  (1 pass) ----
#pragma unroll
        for (int ks2 = 0; ks2 < 4; ks2++) {
            uint32_t pah[4];
            pah[0] = pack2h(s[2 * ks2][0],     s[2 * ks2][1]);
            pah[1] = pack2h(s[2 * ks2][2],     s[2 * ks2][3]);
            pah[2] = pack2h(s[2 * ks2 + 1][0], s[2 * ks2 + 1][1]);
            pah[3] = pack2h(s[2 * ks2 + 1][2], s[2 * ks2 + 1][3]);
            uint32_t vbh[8][2];
#pragma unroll
            for (int nfp = 0; nfp < 4; nfp++) {
                uint32_t addr = st + AV_HI + (uint32_t)(nfp * 16 + b_lrow) * 144 + ks2 * 32 + b_koff;
                ldsm4(addr, vbh[2 * nfp][0], vbh[2 * nfp][1], vbh[2 * nfp + 1][0], vbh[2 * nfp + 1][1]);
            }
#pragma unroll
            for (int nf = 0; nf < 8; nf++) mma_f32(o[nf], pah, vbh[nf]);
        }
    }

    // ---- epilogue: normalize, write ctx (hi only) ----
    const int b = bh / HEADS;
    const int h = bh % HEADS;
    const float inv0 = 1.0f / l_run0;
    const float inv1 = 1.0f / l_run1;
    const int r0 = q0 + wid * 16 + (lane >> 2);
#pragma unroll
    for (int nf = 0; nf < 8; nf++) {
        const int d = nf * 8 + (lane & 3) * 2;
        size_t off = ((size_t)(b * SEQ + r0)) * CDIM + h * HDIM + d;
        *reinterpret_cast<uint32_t*>(g_ctx_hi + off) = pack2h(o[nf][0] * inv0, o[nf][1] * inv0);
        off = ((size_t)(b * SEQ + r0 + 8)) * CDIM + h * HDIM + d;
        *reinterpret_cast<uint32_t*>(g_ctx_hi + off) = pack2h(o[nf][2] * inv1, o[nf][3] * inv1);
    }
}

// ---------------------------------------------------------------------------
// Launch
// ---------------------------------------------------------------------------
extern "C" void kernel_launch(void* const* d_in, const int* in_sizes, int n_in,
                              void* d_out, int out_size)
{
    const float* x      = (const float*)d_in[0];
    const float* w_qkv  = (const float*)d_in[1];
    const float* w_proj = (const float*)d_in[2];
    const float* b_proj = (const float*)d_in[3];
    float* out = (float*)d_out;
    (void)in_sizes; (void)n_in; (void)out_size;

    cudaFuncSetAttribute(qkv_mma,  cudaFuncAttributeMaxDynamicSharedMemorySize, GEMM_SMEM);
    cudaFuncSetAttribute(attn_mma, cudaFuncAttributeMaxDynamicSharedMemorySize, ATTN_SMEM);
    cudaFuncSetAttribute(proj_mma, cudaFuncAttributeMaxDynamicSharedMemorySize, GEMM_SMEM);

    __half *xh, *wh, *wl, *ph, *pl;
    cudaGetSymbolAddress((void**)&xh, g_x_hi);
    cudaGetSymbolAddress((void**)&wh, g_wqkv_hi);
    cudaGetSymbolAddress((void**)&wl, g_wqkv_lo);
    cudaGetSymbolAddress((void**)&ph, g_wproj_hi);
    cudaGetSymbolAddress((void**)&pl, g_wproj_lo);

    convert_hi<<<1024, 256>>>(x, xh, MROWS * CDIM);
    convert_split<<<1024, 256>>>(w_qkv, wh, wl, QKV_N * CDIM);
    convert_split<<<512, 256>>>(w_proj, ph, pl, CDIM * CDIM);

    qkv_mma<<<dim3(QKV_N / 128, MROWS / 128), 256, GEMM_SMEM>>>();
    attn_mma<<<dim3(SEQ / 128, BH), 256, ATTN_SMEM>>>();
    proj_mma<<<dim3(CDIM / 128, MROWS / 128), 256, GEMM_SMEM>>>(b_proj, out);
}

// round 10
// speedup vs baseline: 2.3451x; 1.4328x over previous
#include <cuda_runtime.h>
#include <cuda_fp16.h>
#include <cstdint>

#define BATCH   2
#define SEQ     2048
#define CDIM    768
#define HEADS   12
#define HDIM    64
#define QKV_N   2304
#define MROWS   4096
#define BH      24
#define SCALEF  0.125f

// ---------------------------------------------------------------------------
// Scratch (pure fp16, single precision level)
// ---------------------------------------------------------------------------
__device__ __half g_x_hi[MROWS * CDIM];
__device__ __half g_wqkv_hi[QKV_N * CDIM];
__device__ __half g_wproj_hi[CDIM * CDIM];
__device__ __half g_q_hi[BH * SEQ * HDIM];    // [b,h,n,d], pre-scaled by 1/8
__device__ __half g_k_hi[BH * SEQ * HDIM];
__device__ __half g_vt_hi[BH * HDIM * SEQ];   // [b,h,d,n]
__device__ __half g_ctx_hi[MROWS * CDIM];

// ---------------------------------------------------------------------------
// Helpers
// ---------------------------------------------------------------------------
__device__ __forceinline__ uint32_t smem_u32(const void* p) {
    uint32_t a;
    asm("{ .reg .u64 t; cvta.to.shared.u64 t, %1; cvt.u32.u64 %0, t; }" : "=r"(a) : "l"(p));
    return a;
}
__device__ __forceinline__ void cp16(uint32_t dst, const void* src) {
    asm volatile("cp.async.cg.shared.global [%0], [%1], 16;" :: "r"(dst), "l"(src));
}
__device__ __forceinline__ void cp_commit() { asm volatile("cp.async.commit_group;"); }
template <int N> __device__ __forceinline__ void cp_wait() {
    asm volatile("cp.async.wait_group %0;" :: "n"(N));
}
__device__ __forceinline__ void ldsm4(uint32_t a, uint32_t& r0, uint32_t& r1, uint32_t& r2, uint32_t& r3) {
    asm volatile("ldmatrix.sync.aligned.m8n8.x4.shared.b16 {%0,%1,%2,%3}, [%4];"
                 : "=r"(r0), "=r"(r1), "=r"(r2), "=r"(r3) : "r"(a));
}
__device__ __forceinline__ void mma_f32(float* c, const uint32_t* a, const uint32_t* b) {
    asm volatile("mma.sync.aligned.m16n8k16.row.col.f32.f16.f16.f32 "
                 "{%0,%1,%2,%3}, {%4,%5,%6,%7}, {%8,%9}, {%0,%1,%2,%3};"
                 : "+f"(c[0]), "+f"(c[1]), "+f"(c[2]), "+f"(c[3])
                 : "r"(a[0]), "r"(a[1]), "r"(a[2]), "r"(a[3]), "r"(b[0]), "r"(b[1]));
}
__device__ __forceinline__ uint32_t pack2h(float x, float y) {
    __half2 H = __halves2half2(__float2half_rn(x), __float2half_rn(y));
    return *reinterpret_cast<uint32_t*>(&H);
}

// ---------------------------------------------------------------------------
// Convert fp32 -> fp16
// ---------------------------------------------------------------------------
__global__ void convert_hi(const float* __restrict__ src, __half* __restrict__ hi, int n)
{
    int i = blockIdx.x * blockDim.x + threadIdx.x;
    for (; i < n; i += gridDim.x * blockDim.x)
        hi[i] = __float2half_rn(src[i]);
}

// ---------------------------------------------------------------------------
// GEMM core: C(128x128) = Ah Bh^T over K=768, single pass. 256 threads,
// 8 warps, warp tile 64x32. smem stage: [Ahi 10240][Bhi 10240] @ 80B pitch.
// ---------------------------------------------------------------------------
#define GSTAGE   20480
#define G_BHI    10240
#define GEMM_SMEM (2 * GSTAGE)

__device__ __forceinline__ void gemm_load_stage(
    uint32_t sb, const __half* Ahi, const __half* Bhi,
    int m0, int n0, int k0, int tid)
{
    const int row = tid >> 1;
    const int cb  = (tid & 1) * 32;
    const size_t ga = (size_t)(m0 + row) * CDIM + k0;
    const size_t gb = (size_t)(n0 + row) * CDIM + k0;
    const uint32_t so = (uint32_t)row * 80 + cb;
    cp16(sb + so,               (const char*)(Ahi + ga) + cb);
    cp16(sb + so + 16,          (const char*)(Ahi + ga) + cb + 16);
    cp16(sb + G_BHI + so,       (const char*)(Bhi + gb) + cb);
    cp16(sb + G_BHI + so + 16,  (const char*)(Bhi + gb) + cb + 16);
}

__device__ __forceinline__ void ld_afrag(uint32_t st, int wm, int step,
                                         uint32_t a_lrow, uint32_t a_koff, uint32_t* a)
{
    const int ks = step >> 2, mf = step & 3;
    uint32_t addr = st + (uint32_t)(wm * 64 + mf * 16 + a_lrow) * 80 + ks * 32 + a_koff;
    ldsm4(addr, a[0], a[1], a[2], a[3]);
}
__device__ __forceinline__ void ld_bfrag(uint32_t st, int wn, int ks,
                                         uint32_t b_lrow, uint32_t b_koff,
                                         uint32_t bh[4][2])
{
#pragma unroll
    for (int nfp = 0; nfp < 2; nfp++) {
        uint32_t addr = st + G_BHI + (uint32_t)(wn * 32 + nfp * 16 + b_lrow) * 80 + ks * 32 + b_koff;
        ldsm4(addr, bh[2 * nfp][0], bh[2 * nfp][1], bh[2 * nfp + 1][0], bh[2 * nfp + 1][1]);
    }
}

__device__ __forceinline__ void gemm_core(
    char* smem, const __half* Ahi, const __half* Bhi,
    int m0, int n0, float c[4][4][4])
{
    const int tid = threadIdx.x;
    const int lane = tid & 31;
    const int wid = tid >> 5;
    const int wm = wid >> 2, wn = wid & 3;
    const uint32_t sb = smem_u32(smem);

    const uint32_t a_lrow = lane % 16, a_koff = (lane >> 4) * 16;
    const uint32_t b_lrow = (lane % 8) + ((lane >> 4) << 3), b_koff = ((lane >> 3) & 1) * 16;

#pragma unroll
    for (int i = 0; i < 4; i++)
#pragma unroll
        for (int j = 0; j < 4; j++)
#pragma unroll
            for (int e = 0; e < 4; e++) c[i][j][e] = 0.0f;

    gemm_load_stage(sb, Ahi, Bhi, m0, n0, 0, tid);
    cp_commit();

    uint32_t ar[2][4];
    uint32_t bhr[2][4][2];

    for (int it = 0; it < 24; it++) {
        cp_wait<0>();
        __syncthreads();
        if (it + 1 < 24) {
            gemm_load_stage(sb + ((it + 1) & 1) * GSTAGE, Ahi, Bhi, m0, n0, (it + 1) * 32, tid);
            cp_commit();
        }
        const uint32_t st = sb + (it & 1) * GSTAGE;

        ld_bfrag(st, wn, 0, b_lrow, b_koff, bhr[0]);
        ld_afrag(st, wm, 0, a_lrow, a_koff, ar[0]);

#pragma unroll
        for (int ks = 0; ks < 2; ks++) {
            if (ks == 0)
                ld_bfrag(st, wn, 1, b_lrow, b_koff, bhr[1]);
#pragma unroll
            for (int mf = 0; mf < 4; mf++) {
                const int step = ks * 4 + mf;
                if (step + 1 < 8)
                    ld_afrag(st, wm, step + 1, a_lrow, a_koff, ar[(step + 1) & 1]);
                const uint32_t* a = ar[step & 1];
#pragma unroll
                for (int nf = 0; nf < 4; nf++)
                    mma_f32(c[mf][nf], a, bhr[ks][nf]);
            }
        }
    }
}

// ---------------------------------------------------------------------------
// QKV GEMM: grid (18, 32), 256 threads, 2 CTAs/SM
// ---------------------------------------------------------------------------
__device__ __forceinline__ void qkv_store(int s, int rowg, int colg, float v0, float v1)
{
    const int b = rowg >> 11, n = rowg & 2047;
    const int rem = colg - s * CDIM;
    const int h = rem >> 6, d = rem & 63;
    if (s == 0) {
        const size_t off = ((size_t)(b * HEADS + h) * SEQ + n) * HDIM + d;
        *reinterpret_cast<uint32_t*>(g_q_hi + off) = pack2h(v0 * SCALEF, v1 * SCALEF);
    } else if (s == 1) {
        const size_t off = ((size_t)(b * HEADS + h) * SEQ + n) * HDIM + d;
        *reinterpret_cast<uint32_t*>(g_k_hi + off) = pack2h(v0, v1);
    } else {
        const size_t base = ((size_t)(b * HEADS + h) * HDIM) * SEQ;
        g_vt_hi[base + (size_t)d * SEQ + n]       = __float2half_rn(v0);
        g_vt_hi[base + (size_t)(d + 1) * SEQ + n] = __float2half_rn(v1);
    }
}

__global__ __launch_bounds__(256, 2) void qkv_mma()
{
    extern __shared__ char smem[];
    const int n0 = blockIdx.x * 128;
    const int m0 = blockIdx.y * 128;
    const int lane = threadIdx.x & 31;
    const int wid = threadIdx.x >> 5;
    const int wm = wid >> 2, wn = wid & 3;

    float c[4][4][4];
    gemm_core(smem, g_x_hi, g_wqkv_hi, m0, n0, c);

    const int s = n0 / CDIM;
#pragma unroll
    for (int mf = 0; mf < 4; mf++)
#pragma unroll
        for (int nf = 0; nf < 4; nf++) {
            const int rg = m0 + wm * 64 + mf * 16 + (lane >> 2);
            const int cg = n0 + wn * 32 + nf * 8 + (lane & 3) * 2;
            qkv_store(s, rg,     cg, c[mf][nf][0], c[mf][nf][1]);
            qkv_store(s, rg + 8, cg, c[mf][nf][2], c[mf][nf][3]);
        }
}

// ---------------------------------------------------------------------------
// Output projection: grid (6, 32), 256 threads, 2 CTAs/SM
// ---------------------------------------------------------------------------
__global__ __launch_bounds__(256, 2) void proj_mma(const float* __restrict__ bias,
                                                   float* __restrict__ out)
{
    extern __shared__ char smem[];
    const int n0 = blockIdx.x * 128;
    const int m0 = blockIdx.y * 128;
    const int lane = threadIdx.x & 31;
    const int wid = threadIdx.x >> 5;
    const int wm = wid >> 2, wn = wid & 3;

    float c[4][4][4];
    gemm_core(smem, g_ctx_hi, g_wproj_hi, m0, n0, c);

#pragma unroll
    for (int mf = 0; mf < 4; mf++)
#pragma unroll
        for (int nf = 0; nf < 4; nf++) {
            const int rg = m0 + wm * 64 + mf * 16 + (lane >> 2);
            const int cg = n0 + wn * 32 + nf * 8 + (lane & 3) * 2;
            const float b0 = bias[cg], b1 = bias[cg + 1];
            float2 v0 = make_float2(c[mf][nf][0] + b0, c[mf][nf][1] + b1);
            float2 v1 = make_float2(c[mf][nf][2] + b0, c[mf][nf][3] + b1);
            *reinterpret_cast<float2*>(out + (size_t)rg * CDIM + cg) = v0;
            *reinterpret_cast<float2*>(out + (size_t)(rg + 8) * CDIM + cg) = v1;
        }
}

// ---------------------------------------------------------------------------
// Flash attention: grid (16, 24), 256 threads, 2 CTAs/SM.
// QK = qh·kh [1 pass]; PV = p16·vh [1 pass]. S/P in registers.
// smem: Qhi 18432 | 2 stages x [Khi 9216 | Vthi 9216]
// ---------------------------------------------------------------------------
#define AKV      18432
#define ASTAGE   18432
#define AV_HI    9216
#define ATTN_SMEM (AKV + 2 * ASTAGE)   // 55296

__device__ __forceinline__ void attn_load_stage(
    uint32_t sb, const __half* Kh, const __half* Vh, int kv0, int tid)
{
    const int row = tid >> 2;                 // 0..63
    const int cb  = (tid & 3) * 32;
    const uint32_t so = (uint32_t)row * 144 + cb;
    const char* kh = (const char*)(Kh + (size_t)(kv0 + row) * HDIM) + cb;
    const char* vh = (const char*)(Vh + (size_t)row * SEQ + kv0) + cb;
    cp16(sb + so, kh);            cp16(sb + so + 16, kh + 16);
    cp16(sb + AV_HI + so, vh);    cp16(sb + AV_HI + so + 16, vh + 16);
}

__global__ __launch_bounds__(256, 2) void attn_mma()
{
    extern __shared__ char smem[];
    const uint32_t sb = smem_u32(smem);
    const int q0 = blockIdx.x * 128;
    const int bh = blockIdx.y;
    const int tid = threadIdx.x;
    const int lane = tid & 31;
    const int wid = tid >> 5;

    const __half* Qh = g_q_hi + (size_t)bh * SEQ * HDIM;
    const __half* Kh = g_k_hi + (size_t)bh * SEQ * HDIM;
    const __half* Vh = g_vt_hi + (size_t)bh * HDIM * SEQ;

    // Load Q tile (144B pitch)
    {
        const int row = tid >> 1;
        const int cb = (tid & 1) * 64;
        const uint4* qs = reinterpret_cast<const uint4*>((const char*)(Qh + (size_t)(q0 + row) * HDIM) + cb);
        uint4* dh = reinterpret_cast<uint4*>(smem + (uint32_t)row * 144 + cb);
#pragma unroll
        for (int i = 0; i < 4; i++) dh[i] = qs[i];
    }
    attn_load_stage(sb + AKV, Kh, Vh, 0, tid);
    cp_commit();
    __syncthreads();

    const uint32_t a_lrow = lane % 16, a_koff = (lane >> 4) * 16;
    const uint32_t b_lrow = (lane % 8) + ((lane >> 4) << 3), b_koff = ((lane >> 3) & 1) * 16;

    uint32_t qh[4][4];
#pragma unroll
    for (int ks = 0; ks < 4; ks++) {
        uint32_t addr = sb + (uint32_t)(wid * 16 + a_lrow) * 144 + ks * 32 + a_koff;
        ldsm4(addr, qh[ks][0], qh[ks][1], qh[ks][2], qh[ks][3]);
    }

    float o[8][4];
#pragma unroll
    for (int nf = 0; nf < 8; nf++)
#pragma unroll
        for (int e = 0; e < 4; e++) o[nf][e] = 0.0f;
    float m_run0 = -1e30f, m_run1 = -1e30f, l_run0 = 0.0f, l_run1 = 0.0f;

    for (int it = 0; it < SEQ / 64; it++) {
        cp_wait<0>();
        __syncthreads();
        if (it + 1 < SEQ / 64) {
            attn_load_stage(sb + AKV + ((it + 1) & 1) * ASTAGE, Kh, Vh, (it + 1) * 64, tid);
            cp_commit();
        }
        const uint32_t st = sb + AKV + (it & 1) * ASTAGE;

        // ---- S = qh kh^T (1 pass) ----
        float s[8][4];
#pragma unroll
        for (int nf = 0; nf < 8; nf++)
#pragma unroll
            for (int e = 0; e < 4; e++) s[nf][e] = 0.0f;
#pragma unroll
        for (int ks = 0; ks < 4; ks++) {
            uint32_t kbh[8][2];
#pragma unroll
            for (int nfp = 0; nfp < 4; nfp++) {
                uint32_t addr = st + (uint32_t)(nfp * 16 + b_lrow) * 144 + ks * 32 + b_koff;
                ldsm4(addr, kbh[2 * nfp][0], kbh[2 * nfp][1], kbh[2 * nfp + 1][0], kbh[2 * nfp + 1][1]);
            }
#pragma unroll
            for (int nf = 0; nf < 8; nf++)
                mma_f32(s[nf], qh[ks], kbh[nf]);
        }

        // ---- online softmax ----
        float vm0 = -1e30f, vm1 = -1e30f;
#pragma unroll
        for (int nf = 0; nf < 8; nf++) {
            vm0 = fmaxf(vm0, fmaxf(s[nf][0], s[nf][1]));
            vm1 = fmaxf(vm1, fmaxf(s[nf][2], s[nf][3]));
        }
        vm0 = fmaxf(vm0, __shfl_xor_sync(0xffffffff, vm0, 1));
        vm0 = fmaxf(vm0, __shfl_xor_sync(0xffffffff, vm0, 2));
        vm1 = fmaxf(vm1, __shfl_xor_sync(0xffffffff, vm1, 1));
        vm1 = fmaxf(vm1, __shfl_xor_sync(0xffffffff, vm1, 2));
        const float nm0 = fmaxf(m_run0, vm0);
        const float nm1 = fmaxf(m_run1, vm1);
        const float corr0 = __expf(m_run0 - nm0);
        const float corr1 = __expf(m_run1 - nm1);
        float sum0 = 0.0f, sum1 = 0.0f;
#pragma unroll
        for (int nf = 0; nf < 8; nf++) {
            s[nf][0] = __expf(s[nf][0] - nm0); sum0 += s[nf][0];
            s[nf][1] = __expf(s[nf][1] - nm0); sum0 += s[nf][1];
            s[nf][2] = __expf(s[nf][2] - nm1); sum1 += s[nf][2];
            s[nf][3] = __expf(s[nf][3] - nm1); sum1 += s[nf][3];
        }
        sum0 += __shfl_xor_sync(0xffffffff, sum0, 1);
        sum0 += __shfl_xor_sync(0xffffffff, sum0, 2);
        sum1 += __shfl_xor_sync(0xffffffff, sum1, 1);
        sum1 += __shfl_xor_sync(0xffffffff, sum1, 2);
        l_run0 = l_run0 * corr0 + sum0;
        l_run1 = l_run1 * corr1 + sum1;
        m_run0 = nm0; m_run1 = nm1;
#pragma unroll
        for (int nf = 0; nf < 8; nf++) {
            o[nf][0] *= corr0; o[nf][1] *= corr0;
            o[nf][2] *= corr1; o[nf][3] *= corr1;
        }

        // ---- O += p16 · vh (1 pass) ----
#pragma unroll
        for (int ks2 = 0; ks2 < 4; ks2++) {
            uint32_t pah[4];
            pah[0] = pack2h(s[2 * ks2][0],     s[2 * ks2][1]);
            pah[1] = pack2h(s[2 * ks2][2],     s[2 * ks2][3]);
            pah[2] = pack2h(s[2 * ks2 + 1][0], s[2 * ks2 + 1][1]);
            pah[3] = pack2h(s[2 * ks2 + 1][2], s[2 * ks2 + 1][3]);
            uint32_t vbh[8][2];
#pragma unroll
            for (int nfp = 0; nfp < 4; nfp++) {
                uint32_t addr = st + AV_HI + (uint32_t)(nfp * 16 + b_lrow) * 144 + ks2 * 32 + b_koff;
                ldsm4(addr, vbh[2 * nfp][0], vbh[2 * nfp][1], vbh[2 * nfp + 1][0], vbh[2 * nfp + 1][1]);
            }
#pragma unroll
            for (int nf = 0; nf < 8; nf++)
                mma_f32(o[nf], pah, vbh[nf]);
        }
    }

    // ---- epilogue: normalize, write ctx ----
    const int b = bh / HEADS;
    const int h = bh % HEADS;
    const float inv0 = 1.0f / l_run0;
    const float inv1 = 1.0f / l_run1;
    const int r0 = q0 + wid * 16 + (lane >> 2);
#pragma unroll
    for (int nf = 0; nf < 8; nf++) {
        const int d = nf * 8 + (lane & 3) * 2;
        size_t off = ((size_t)(b * SEQ + r0)) * CDIM + h * HDIM + d;
        *reinterpret_cast<uint32_t*>(g_ctx_hi + off) = pack2h(o[nf][0] * inv0, o[nf][1] * inv0);
        off = ((size_t)(b * SEQ + r0 + 8)) * CDIM + h * HDIM + d;
        *reinterpret_cast<uint32_t*>(g_ctx_hi + off) = pack2h(o[nf][2] * inv1, o[nf][3] * inv1);
    }
}

// ---------------------------------------------------------------------------
// Launch
// ---------------------------------------------------------------------------
extern "C" void kernel_launch(void* const* d_in, const int* in_sizes, int n_in,
                              void* d_out, int out_size)
{
    const float* x      = (const float*)d_in[0];
    const float* w_qkv  = (const float*)d_in[1];
    const float* w_proj = (const float*)d_in[2];
    const float* b_proj = (const float*)d_in[3];
    float* out = (float*)d_out;
    (void)in_sizes; (void)n_in; (void)out_size;

    cudaFuncSetAttribute(qkv_mma,  cudaFuncAttributeMaxDynamicSharedMemorySize, GEMM_SMEM);
    cudaFuncSetAttribute(attn_mma, cudaFuncAttributeMaxDynamicSharedMemorySize, ATTN_SMEM);
    cudaFuncSetAttribute(proj_mma, cudaFuncAttributeMaxDynamicSharedMemorySize, GEMM_SMEM);

    __half *xh, *wh, *ph;
    cudaGetSymbolAddress((void**)&xh, g_x_hi);
    cudaGetSymbolAddress((void**)&wh, g_wqkv_hi);
    cudaGetSymbolAddress((void**)&ph, g_wproj_hi);

    convert_hi<<<1024, 256>>>(x, xh, MROWS * CDIM);
    convert_hi<<<1024, 256>>>(w_qkv, wh, QKV_N * CDIM);
    convert_hi<<<512, 256>>>(w_proj, ph, CDIM * CDIM);

    qkv_mma<<<dim3(QKV_N / 128, MROWS / 128), 256, GEMM_SMEM>>>();
    attn_mma<<<dim3(SEQ / 128, BH), 256, ATTN_SMEM>>>();
    proj_mma<<<dim3(CDIM / 128, MROWS / 128), 256, GEMM_SMEM>>>(b_proj, out);
}

// round 11
// speedup vs baseline: 2.3632x; 1.0077x over previous
#include <cuda_runtime.h>
#include <cuda_fp16.h>
#include <cstdint>

#define BATCH   2
#define SEQ     2048
#define CDIM    768
#define HEADS   12
#define HDIM    64
#define QKV_N   2304
#define MROWS   4096
#define BH      24
#define SCALEF  0.125f

// ---------------------------------------------------------------------------
// Scratch (pure fp16)
// ---------------------------------------------------------------------------
__device__ __half g_x_hi[MROWS * CDIM];
__device__ __half g_wqkv_hi[QKV_N * CDIM];
__device__ __half g_wproj_hi[CDIM * CDIM];
__device__ __half g_q_hi[BH * SEQ * HDIM];    // [b,h,n,d], pre-scaled by 1/8
__device__ __half g_k_hi[BH * SEQ * HDIM];
__device__ __half g_vt_hi[BH * HDIM * SEQ];   // [b,h,d,n]
__device__ __half g_ctx_hi[MROWS * CDIM];

// ---------------------------------------------------------------------------
// Helpers
// ---------------------------------------------------------------------------
__device__ __forceinline__ uint32_t smem_u32(const void* p) {
    uint32_t a;
    asm("{ .reg .u64 t; cvta.to.shared.u64 t, %1; cvt.u32.u64 %0, t; }" : "=r"(a) : "l"(p));
    return a;
}
__device__ __forceinline__ void cp16(uint32_t dst, const void* src) {
    asm volatile("cp.async.cg.shared.global [%0], [%1], 16;" :: "r"(dst), "l"(src));
}
__device__ __forceinline__ void cp_commit() { asm volatile("cp.async.commit_group;"); }
template <int N> __device__ __forceinline__ void cp_wait() {
    asm volatile("cp.async.wait_group %0;" :: "n"(N));
}
__device__ __forceinline__ void ldsm4(uint32_t a, uint32_t& r0, uint32_t& r1, uint32_t& r2, uint32_t& r3) {
    asm volatile("ldmatrix.sync.aligned.m8n8.x4.shared.b16 {%0,%1,%2,%3}, [%4];"
                 : "=r"(r0), "=r"(r1), "=r"(r2), "=r"(r3) : "r"(a));
}
__device__ __forceinline__ void mma_f32(float* c, const uint32_t* a, const uint32_t* b) {
    asm volatile("mma.sync.aligned.m16n8k16.row.col.f32.f16.f16.f32 "
                 "{%0,%1,%2,%3}, {%4,%5,%6,%7}, {%8,%9}, {%0,%1,%2,%3};"
                 : "+f"(c[0]), "+f"(c[1]), "+f"(c[2]), "+f"(c[3])
                 : "r"(a[0]), "r"(a[1]), "r"(a[2]), "r"(a[3]), "r"(b[0]), "r"(b[1]));
}
__device__ __forceinline__ uint32_t pack2h(float x, float y) {
    __half2 H = __halves2half2(__float2half_rn(x), __float2half_rn(y));
    return *reinterpret_cast<uint32_t*>(&H);
}

// ---------------------------------------------------------------------------
// Convert fp32 -> fp16
// ---------------------------------------------------------------------------
__global__ void convert_hi(const float* __restrict__ src, __half* __restrict__ hi, int n)
{
    int i = blockIdx.x * blockDim.x + threadIdx.x;
    for (; i < n; i += gridDim.x * blockDim.x)
        hi[i] = __float2half_rn(src[i]);
}

// ---------------------------------------------------------------------------
// GEMM core: C(128x128) = Ah Bh^T over K=768, single pass. 256 threads,
// 8 warps, warp tile 64x32. 3-stage cp.async pipeline (cp_wait<1>).
// smem stage: [Ahi 10240][Bhi 10240] @ 80B pitch.
// ---------------------------------------------------------------------------
#define GSTAGE   20480
#define G_BHI    10240
#define GEMM_SMEM (3 * GSTAGE)

__device__ __forceinline__ void gemm_load_stage(
    uint32_t sb, const __half* Ahi, const __half* Bhi,
    int m0, int n0, int k0, int tid)
{
    const int row = tid >> 1;
    const int cb  = (tid & 1) * 32;
    const size_t ga = (size_t)(m0 + row) * CDIM + k0;
    const size_t gb = (size_t)(n0 + row) * CDIM + k0;
    const uint32_t so = (uint32_t)row * 80 + cb;
    cp16(sb + so,               (const char*)(Ahi + ga) + cb);
    cp16(sb + so + 16,          (const char*)(Ahi + ga) + cb + 16);
    cp16(sb + G_BHI + so,       (const char*)(Bhi + gb) + cb);
    cp16(sb + G_BHI + so + 16,  (const char*)(Bhi + gb) + cb + 16);
}

__device__ __forceinline__ void ld_afrag(uint32_t st, int wm, int step,
                                         uint32_t a_lrow, uint32_t a_koff, uint32_t* a)
{
    const int ks = step >> 2, mf = step & 3;
    uint32_t addr = st + (uint32_t)(wm * 64 + mf * 16 + a_lrow) * 80 + ks * 32 + a_koff;
    ldsm4(addr, a[0], a[1], a[2], a[3]);
}
__device__ __forceinline__ void ld_bfrag(uint32_t st, int wn, int ks,
                                         uint32_t b_lrow, uint32_t b_koff,
                                         uint32_t bh[4][2])
{
#pragma unroll
    for (int nfp = 0; nfp < 2; nfp++) {
        uint32_t addr = st + G_BHI + (uint32_t)(wn * 32 + nfp * 16 + b_lrow) * 80 + ks * 32 + b_koff;
        ldsm4(addr, bh[2 * nfp][0], bh[2 * nfp][1], bh[2 * nfp + 1][0], bh[2 * nfp + 1][1]);
    }
}

__device__ __forceinline__ void gemm_core(
    char* smem, const __half* Ahi, const __half* Bhi,
    int m0, int n0, float c[4][4][4])
{
    const int tid = threadIdx.x;
    const int lane = tid & 31;
    const int wid = tid >> 5;
    const int wm = wid >> 2, wn = wid & 3;
    const uint32_t sb = smem_u32(smem);

    const uint32_t a_lrow = lane % 16, a_koff = (lane >> 4) * 16;
    const uint32_t b_lrow = (lane % 8) + ((lane >> 4) << 3), b_koff = ((lane >> 3) & 1) * 16;

#pragma unroll
    for (int i = 0; i < 4; i++)
#pragma unroll
        for (int j = 0; j < 4; j++)
#pragma unroll
            for (int e = 0; e < 4; e++) c[i][j][e] = 0.0f;

    // prologue: prefetch stages 0 and 1
    gemm_load_stage(sb + 0 * GSTAGE, Ahi, Bhi, m0, n0, 0, tid);
    cp_commit();
    gemm_load_stage(sb + 1 * GSTAGE, Ahi, Bhi, m0, n0, 32, tid);
    cp_commit();

    uint32_t ar[2][4];
    uint32_t bhr[2][4][2];

    for (int it = 0; it < 24; it++) {
        if (it + 2 < 24) cp_wait<1>(); else cp_wait<0>();
        __syncthreads();
        if (it + 2 < 24) {
            gemm_load_stage(sb + ((it + 2) % 3) * GSTAGE, Ahi, Bhi, m0, n0, (it + 2) * 32, tid);
            cp_commit();
        }
        const uint32_t st = sb + (it % 3) * GSTAGE;

        ld_bfrag(st, wn, 0, b_lrow, b_koff, bhr[0]);
        ld_afrag(st, wm, 0, a_lrow, a_koff, ar[0]);

#pragma unroll
        for (int ks = 0; ks < 2; ks++) {
            if (ks == 0)
                ld_bfrag(st, wn, 1, b_lrow, b_koff, bhr[1]);
#pragma unroll
            for (int mf = 0; mf < 4; mf++) {
                const int step = ks * 4 + mf;
                if (step + 1 < 8)
                    ld_afrag(st, wm, step + 1, a_lrow, a_koff, ar[(step + 1) & 1]);
                const uint32_t* a = ar[step & 1];
#pragma unroll
                for (int nf = 0; nf < 4; nf++)
                    mma_f32(c[mf][nf], a, bhr[ks][nf]);
            }
        }
    }
}

// ---------------------------------------------------------------------------
// QKV GEMM: grid (18, 32), 256 threads, 2 CTAs/SM
// ---------------------------------------------------------------------------
__device__ __forceinline__ void qkv_store(int s, int rowg, int colg, float v0, float v1)
{
    const int b = rowg >> 11, n = rowg & 2047;
    const int rem = colg - s * CDIM;
    const int h = rem >> 6, d = rem & 63;
    if (s == 0) {
        const size_t off = ((size_t)(b * HEADS + h) * SEQ + n) * HDIM + d;
        *reinterpret_cast<uint32_t*>(g_q_hi + off) = pack2h(v0 * SCALEF, v1 * SCALEF);
    } else if (s == 1) {
        const size_t off = ((size_t)(b * HEADS + h) * SEQ + n) * HDIM + d;
        *reinterpret_cast<uint32_t*>(g_k_hi + off) = pack2h(v0, v1);
    } else {
        const size_t base = ((size_t)(b * HEADS + h) * HDIM) * SEQ;
        g_vt_hi[base + (size_t)d * SEQ + n]       = __float2half_rn(v0);
        g_vt_hi[base + (size_t)(d + 1) * SEQ + n] = __float2half_rn(v1);
    }
}

__global__ __launch_bounds__(256, 2) void qkv_mma()
{
    extern __shared__ char smem[];
    const int n0 = blockIdx.x * 128;
    const int m0 = blockIdx.y * 128;
    const int lane = threadIdx.x & 31;
    const int wid = threadIdx.x >> 5;
    const int wm = wid >> 2, wn = wid & 3;

    float c[4][4][4];
    gemm_core(smem, g_x_hi, g_wqkv_hi, m0, n0, c);

    const int s = n0 / CDIM;
#pragma unroll
    for (int mf = 0; mf < 4; mf++)
#pragma unroll
        for (int nf = 0; nf < 4; nf++) {
            const int rg = m0 + wm * 64 + mf * 16 + (lane >> 2);
            const int cg = n0 + wn * 32 + nf * 8 + (lane & 3) * 2;
            qkv_store(s, rg,     cg, c[mf][nf][0], c[mf][nf][1]);
            qkv_store(s, rg + 8, cg, c[mf][nf][2], c[mf][nf][3]);
        }
}

// ---------------------------------------------------------------------------
// Output projection: grid (6, 32), 256 threads, 2 CTAs/SM
// ---------------------------------------------------------------------------
__global__ __launch_bounds__(256, 2) void proj_mma(const float* __restrict__ bias,
                                                   float* __restrict__ out)
{
    extern __shared__ char smem[];
    const int n0 = blockIdx.x * 128;
    const int m0 = blockIdx.y * 128;
    const int lane = threadIdx.x & 31;
    const int wid = threadIdx.x >> 5;
    const int wm = wid >> 2, wn = wid & 3;

    float c[4][4][4];
    gemm_core(smem, g_ctx_hi, g_wproj_hi, m0, n0, c);

#pragma unroll
    for (int mf = 0; mf < 4; mf++)
#pragma unroll
        for (int nf = 0; nf < 4; nf++) {
            const int rg = m0 + wm * 64 + mf * 16 + (lane >> 2);
            const int cg = n0 + wn * 32 + nf * 8 + (lane & 3) * 2;
            const float b0 = bias[cg], b1 = bias[cg + 1];
            float2 v0 = make_float2(c[mf][nf][0] + b0, c[mf][nf][1] + b1);
            float2 v1 = make_float2(c[mf][nf][2] + b0, c[mf][nf][3] + b1);
            *reinterpret_cast<float2*>(out + (size_t)rg * CDIM + cg) = v0;
            *reinterpret_cast<float2*>(out + (size_t)(rg + 8) * CDIM + cg) = v1;
        }
}

// ---------------------------------------------------------------------------
// Flash attention: grid (16, 24), 256 threads, 2 CTAs/SM. 3-stage KV pipeline.
// smem: Qhi 18432 | 3 stages x [Khi 9216 | Vthi 9216]
// ---------------------------------------------------------------------------
#define AKV      18432
#define ASTAGE   18432
#define AV_HI    9216
#define ATTN_SMEM (AKV + 3 * ASTAGE)   // 73728

__device__ __forceinline__ void attn_load_stage(
    uint32_t sb, const __half* Kh, const __half* Vh, int kv0, int tid)
{
    const int row = tid >> 2;                 // 0..63
    const int cb  = (tid & 3) * 32;
    const uint32_t so = (uint32_t)row * 144 + cb;
    const char* kh = (const char*)(Kh + (size_t)(kv0 + row) * HDIM) + cb;
    const char* vh = (const char*)(Vh + (size_t)row * SEQ + kv0) + cb;
    cp16(sb + so, kh);            cp16(sb + so + 16, kh + 16);
    cp16(sb + AV_HI + so, vh);    cp16(sb + AV_HI + so + 16, vh + 16);
}

__global__ __launch_bounds__(256, 2) void attn_mma()
{
    extern __shared__ char smem[];
    const uint32_t sb = smem_u32(smem);
    const int q0 = blockIdx.x * 128;
    const int bh = blockIdx.y;
    const int tid = threadIdx.x;
    const int lane = tid & 31;
    const int wid = tid >> 5;

    const __half* Qh = g_q_hi + (size_t)bh * SEQ * HDIM;
    const __half* Kh = g_k_hi + (size_t)bh * SEQ * HDIM;
    const __half* Vh = g_vt_hi + (size_t)bh * HDIM * SEQ;

    // Load Q tile (144B pitch)
    {
        const int row = tid >> 1;
        const int cb = (tid & 1) * 64;
        const uint4* qs = reinterpret_cast<const uint4*>((const char*)(Qh + (size_t)(q0 + row) * HDIM) + cb);
        uint4* dh = reinterpret_cast<uint4*>(smem + (uint32_t)row * 144 + cb);
#pragma unroll
        for (int i = 0; i < 4; i++) dh[i] = qs[i];
    }
    // prologue: prefetch kv stages 0 and 1
    attn_load_stage(sb + AKV + 0 * ASTAGE, Kh, Vh, 0, tid);
    cp_commit();
    attn_load_stage(sb + AKV + 1 * ASTAGE, Kh, Vh, 64, tid);
    cp_commit();
    __syncthreads();

    const uint32_t a_lrow = lane % 16, a_koff = (lane >> 4) * 16;
    const uint32_t b_lrow = (lane % 8) + ((lane >> 4) << 3), b_koff = ((lane >> 3) & 1) * 16;

    uint32_t qh[4][4];
#pragma unroll
    for (int ks = 0; ks < 4; ks++) {
        uint32_t addr = sb + (uint32_t)(wid * 16 + a_lrow) * 144 + ks * 32 + a_koff;
        ldsm4(addr, qh[ks][0], qh[ks][1], qh[ks][2], qh[ks][3]);
    }

    float o[8][4];
#pragma unroll
    for (int nf = 0; nf < 8; nf++)
#pragma unroll
        for (int e = 0; e < 4; e++) o[nf][e] = 0.0f;
    float m_run0 = -1e30f, m_run1 = -1e30f, l_run0 = 0.0f, l_run1 = 0.0f;

    const int NIT = SEQ / 64;   // 32
    for (int it = 0; it < NIT; it++) {
        if (it + 2 < NIT) cp_wait<1>(); else cp_wait<0>();
        __syncthreads();
        if (it + 2 < NIT) {
            attn_load_stage(sb + AKV + ((it + 2) % 3) * ASTAGE, Kh, Vh, (it + 2) * 64, tid);
            cp_commit();
        }
        const uint32_t st = sb + AKV + (it % 3) * ASTAGE;

        // ---- S = qh kh^T (1 pass) ----
        float s[8][4];
#pragma unroll
        for (int nf = 0; nf < 8; nf++)
#pragma unroll
            for (int e = 0; e < 4; e++) s[nf][e] = 0.0f;
#pragma unroll
        for (int ks = 0; ks < 4; ks++) {
            uint32_t kbh[8][2];
#pragma unroll
            for (int nfp = 0; nfp < 4; nfp++) {
                uint32_t addr = st + (uint32_t)(nfp * 16 + b_lrow) * 144 + ks * 32 + b_koff;
                ldsm4(addr, kbh[2 * nfp][0], kbh[2 * nfp][1], kbh[2 * nfp + 1][0], kbh[2 * nfp + 1][1]);
            }
#pragma unroll
            for (int nf = 0; nf < 8; nf++)
                mma_f32(s[nf], qh[ks], kbh[nf]);
        }

        // ---- online softmax ----
        float vm0 = -1e30f, vm1 = -1e30f;
#pragma unroll
        for (int nf = 0; nf < 8; nf++) {
            vm0 = fmaxf(vm0, fmaxf(s[nf][0], s[nf][1]));
            vm1 = fmaxf(vm1, fmaxf(s[nf][2], s[nf][3]));
        }
        vm0 = fmaxf(vm0, __shfl_xor_sync(0xffffffff, vm0, 1));
        vm0 = fmaxf(vm0, __shfl_xor_sync(0xffffffff, vm0, 2));
        vm1 = fmaxf(vm1, __shfl_xor_sync(0xffffffff, vm1, 1));
        vm1 = fmaxf(vm1, __shfl_xor_sync(0xffffffff, vm1, 2));
        const float nm0 = fmaxf(m_run0, vm0);
        const float nm1 = fmaxf(m_run1, vm1);
        const float corr0 = __expf(m_run0 - nm0);
        const float corr1 = __expf(m_run1 - nm1);
        float sum0 = 0.0f, sum1 = 0.0f;
#pragma unroll
        for (int nf = 0; nf < 8; nf++) {
            s[nf][0] = __expf(s[nf][0] - nm0); sum0 += s[nf][0];
            s[nf][1] = __expf(s[nf][1] - nm0); sum0 += s[nf][1];
            s[nf][2] = __expf(s[nf][2] - nm1); sum1 += s[nf][2];
            s[nf][3] = __expf(s[nf][3] - nm1); sum1 += s[nf][3];
        }
        sum0 += __shfl_xor_sync(0xffffffff, sum0, 1);
        sum0 += __shfl_xor_sync(0xffffffff, sum0, 2);
        sum1 += __shfl_xor_sync(0xffffffff, sum1, 1);
        sum1 += __shfl_xor_sync(0xffffffff, sum1, 2);
        l_run0 = l_run0 * corr0 + sum0;
        l_run1 = l_run1 * corr1 + sum1;
        m_run0 = nm0; m_run1 = nm1;
#pragma unroll
        for (int nf = 0; nf < 8; nf++) {
            o[nf][0] *= corr0; o[nf][1] *= corr0;
            o[nf][2] *= corr1; o[nf][3] *= corr1;
        }

        // ---- O += p16 · vh (1 pass) ----
#pragma unroll
        for (int ks2 = 0; ks2 < 4; ks2++) {
            uint32_t pah[4];
            pah[0] = pack2h(s[2 * ks2][0],     s[2 * ks2][1]);
            pah[1] = pack2h(s[2 * ks2][2],     s[2 * ks2][3]);
            pah[2] = pack2h(s[2 * ks2 + 1][0], s[2 * ks2 + 1][1]);
            pah[3] = pack2h(s[2 * ks2 + 1][2], s[2 * ks2 + 1][3]);
            uint32_t vbh[8][2];
#pragma unroll
            for (int nfp = 0; nfp < 4; nfp++) {
                uint32_t addr = st + AV_HI + (uint32_t)(nfp * 16 + b_lrow) * 144 + ks2 * 32 + b_koff;
                ldsm4(addr, vbh[2 * nfp][0], vbh[2 * nfp][1], vbh[2 * nfp + 1][0], vbh[2 * nfp + 1][1]);
            }
#pragma unroll
            for (int nf = 0; nf < 8; nf++)
                mma_f32(o[nf], pah, vbh[nf]);
        }
    }

    // ---- epilogue: normalize, write ctx ----
    const int b = bh / HEADS;
    const int h = bh % HEADS;
    const float inv0 = 1.0f / l_run0;
    const float inv1 = 1.0f / l_run1;
    const int r0 = q0 + wid * 16 + (lane >> 2);
#pragma unroll
    for (int nf = 0; nf < 8; nf++) {
        const int d = nf * 8 + (lane & 3) * 2;
        size_t off = ((size_t)(b * SEQ + r0)) * CDIM + h * HDIM + d;
        *reinterpret_cast<uint32_t*>(g_ctx_hi + off) = pack2h(o[nf][0] * inv0, o[nf][1] * inv0);
        off = ((size_t)(b * SEQ + r0 + 8)) * CDIM + h * HDIM + d;
        *reinterpret_cast<uint32_t*>(g_ctx_hi + off) = pack2h(o[nf][2] * inv1, o[nf][3] * inv1);
    }
}

// ---------------------------------------------------------------------------
// Launch
// ---------------------------------------------------------------------------
extern "C" void kernel_launch(void* const* d_in, const int* in_sizes, int n_in,
                              void* d_out, int out_size)
{
    const float* x      = (const float*)d_in[0];
    const float* w_qkv  = (const float*)d_in[1];
    const float* w_proj = (const float*)d_in[2];
    const float* b_proj = (const float*)d_in[3];
    float* out = (float*)d_out;
    (void)in_sizes; (void)n_in; (void)out_size;

    cudaFuncSetAttribute(qkv_mma,  cudaFuncAttributeMaxDynamicSharedMemorySize, GEMM_SMEM);
    cudaFuncSetAttribute(attn_mma, cudaFuncAttributeMaxDynamicSharedMemorySize, ATTN_SMEM);
    cudaFuncSetAttribute(proj_mma, cudaFuncAttributeMaxDynamicSharedMemorySize, GEMM_SMEM);

    __half *xh, *wh, *ph;
    cudaGetSymbolAddress((void**)&xh, g_x_hi);
    cudaGetSymbolAddress((void**)&wh, g_wqkv_hi);
    cudaGetSymbolAddress((void**)&ph, g_wproj_hi);

    convert_hi<<<1024, 256>>>(x, xh, MROWS * CDIM);
    convert_hi<<<1024, 256>>>(w_qkv, wh, QKV_N * CDIM);
    convert_hi<<<512, 256>>>(w_proj, ph, CDIM * CDIM);

    qkv_mma<<<dim3(QKV_N / 128, MROWS / 128), 256, GEMM_SMEM>>>();
    attn_mma<<<dim3(SEQ / 128, BH), 256, ATTN_SMEM>>>();
    proj_mma<<<dim3(CDIM / 128, MROWS / 128), 256, GEMM_SMEM>>>(b_proj, out);
}